// round 2
// baseline (speedup 1.0000x reference)
#include <cuda_runtime.h>
#include <cuda_bf16.h>

// Problem constants
#define BB   2
#define TT   4096
#define CC   768
#define HH   12
#define DH   64
#define BT   (BB*TT)          // 8192

// Scratch (device globals; allocation-free rule)
__device__ float g_q[BB*HH*TT*DH];   // [b*H+h][t][d]
__device__ float g_k[BB*HH*TT*DH];
__device__ float g_v[BB*HH*TT*DH];
__device__ float g_y[BT*CC];         // [b*T+t][c]

// ---------------------------------------------------------------------------
// GEMM (NT): out[r,c] = sum_k A[r,k] * W[c,k]
// Tile: 128(M) x 64(N), BK=16, 128 threads, 8x8 per thread.
// Column ownership split {tx*4 .. tx*4+3} U {tx*4+32 .. tx*4+35} -> conflict-free
// float4 smem loads in the inner loop.
// ---------------------------------------------------------------------------

__global__ void __launch_bounds__(128) qkv_gemm_kernel(
    const float* __restrict__ X,
    const float* __restrict__ Wq_,
    const float* __restrict__ Wk_,
    const float* __restrict__ Wv_)
{
    __shared__ float As[16][128];
    __shared__ float Bs[16][64];

    const int z  = blockIdx.z;
    const float* W = (z == 0) ? Wq_ : (z == 1) ? Wk_ : Wv_;
    float* dst     = (z == 0) ? g_q : (z == 1) ? g_k : g_v;

    const int cb = blockIdx.x;   // head index (64 cols == one head)
    const int rb = blockIdx.y;   // 0..63 (row tiles of 128)
    const int tid = threadIdx.x;
    const int tx = tid & 7;
    const int ty = tid >> 3;

    const float* Abase = X + (size_t)rb * 128 * CC;
    const float* Bbase = W + (size_t)cb * 64 * CC;

    float acc[8][8];
#pragma unroll
    for (int i = 0; i < 8; i++)
#pragma unroll
        for (int j = 0; j < 8; j++) acc[i][j] = 0.0f;

    const int mld = tid >> 2;           // 0..31
    const int k0  = (tid & 3) * 4;      // 0,4,8,12

    for (int kc = 0; kc < CC / 16; kc++) {
        const float* Ap = Abase + kc * 16;
#pragma unroll
        for (int l = 0; l < 4; l++) {
            int m = mld + l * 32;
            float4 v = *(const float4*)(Ap + (size_t)m * CC + k0);
            As[k0 + 0][m] = v.x; As[k0 + 1][m] = v.y;
            As[k0 + 2][m] = v.z; As[k0 + 3][m] = v.w;
        }
        const float* Bp = Bbase + kc * 16;
#pragma unroll
        for (int l = 0; l < 2; l++) {
            int n = mld + l * 32;
            float4 v = *(const float4*)(Bp + (size_t)n * CC + k0);
            Bs[k0 + 0][n] = v.x; Bs[k0 + 1][n] = v.y;
            Bs[k0 + 2][n] = v.z; Bs[k0 + 3][n] = v.w;
        }
        __syncthreads();
#pragma unroll
        for (int kk = 0; kk < 16; kk++) {
            float4 a0 = *(const float4*)&As[kk][ty * 8];
            float4 a1 = *(const float4*)&As[kk][ty * 8 + 4];
            float4 b0 = *(const float4*)&Bs[kk][tx * 4];
            float4 b1 = *(const float4*)&Bs[kk][tx * 4 + 32];
            float a[8] = {a0.x, a0.y, a0.z, a0.w, a1.x, a1.y, a1.z, a1.w};
            float b[8] = {b0.x, b0.y, b0.z, b0.w, b1.x, b1.y, b1.z, b1.w};
#pragma unroll
            for (int ii = 0; ii < 8; ii++)
#pragma unroll
                for (int jj = 0; jj < 8; jj++)
                    acc[ii][jj] += a[ii] * b[jj];
        }
        __syncthreads();
    }

    // Write to [b*H+h][t][d]; cols of this block == head cb, d == j.
#pragma unroll
    for (int ii = 0; ii < 8; ii++) {
        int r = rb * 128 + ty * 8 + ii;
        int b = r >> 12;
        int t = r & (TT - 1);
        float* drow = dst + ((size_t)(b * HH + cb) * TT + t) * DH;
        *(float4*)(drow + tx * 4) =
            make_float4(acc[ii][0], acc[ii][1], acc[ii][2], acc[ii][3]);
        *(float4*)(drow + tx * 4 + 32) =
            make_float4(acc[ii][4], acc[ii][5], acc[ii][6], acc[ii][7]);
    }
}

__global__ void __launch_bounds__(128) proj_gemm_kernel(
    const float* __restrict__ Wp,
    const float* __restrict__ bp,
    float* __restrict__ out)
{
    __shared__ float As[16][128];
    __shared__ float Bs[16][64];

    const int cb = blockIdx.x;
    const int rb = blockIdx.y;
    const int tid = threadIdx.x;
    const int tx = tid & 7;
    const int ty = tid >> 3;

    const float* Abase = g_y + (size_t)rb * 128 * CC;
    const float* Bbase = Wp + (size_t)cb * 64 * CC;

    float acc[8][8];
#pragma unroll
    for (int i = 0; i < 8; i++)
#pragma unroll
        for (int j = 0; j < 8; j++) acc[i][j] = 0.0f;

    const int mld = tid >> 2;
    const int k0  = (tid & 3) * 4;

    for (int kc = 0; kc < CC / 16; kc++) {
        const float* Ap = Abase + kc * 16;
#pragma unroll
        for (int l = 0; l < 4; l++) {
            int m = mld + l * 32;
            float4 v = *(const float4*)(Ap + (size_t)m * CC + k0);
            As[k0 + 0][m] = v.x; As[k0 + 1][m] = v.y;
            As[k0 + 2][m] = v.z; As[k0 + 3][m] = v.w;
        }
        const float* Bp = Bbase + kc * 16;
#pragma unroll
        for (int l = 0; l < 2; l++) {
            int n = mld + l * 32;
            float4 v = *(const float4*)(Bp + (size_t)n * CC + k0);
            Bs[k0 + 0][n] = v.x; Bs[k0 + 1][n] = v.y;
            Bs[k0 + 2][n] = v.z; Bs[k0 + 3][n] = v.w;
        }
        __syncthreads();
#pragma unroll
        for (int kk = 0; kk < 16; kk++) {
            float4 a0 = *(const float4*)&As[kk][ty * 8];
            float4 a1 = *(const float4*)&As[kk][ty * 8 + 4];
            float4 b0 = *(const float4*)&Bs[kk][tx * 4];
            float4 b1 = *(const float4*)&Bs[kk][tx * 4 + 32];
            float a[8] = {a0.x, a0.y, a0.z, a0.w, a1.x, a1.y, a1.z, a1.w};
            float b[8] = {b0.x, b0.y, b0.z, b0.w, b1.x, b1.y, b1.z, b1.w};
#pragma unroll
            for (int ii = 0; ii < 8; ii++)
#pragma unroll
                for (int jj = 0; jj < 8; jj++)
                    acc[ii][jj] += a[ii] * b[jj];
        }
        __syncthreads();
    }

    // bias
    float bv0[4], bv1[4];
#pragma unroll
    for (int q = 0; q < 4; q++) {
        bv0[q] = bp[cb * 64 + tx * 4 + q];
        bv1[q] = bp[cb * 64 + tx * 4 + 32 + q];
    }

#pragma unroll
    for (int ii = 0; ii < 8; ii++) {
        int r = rb * 128 + ty * 8 + ii;
        float* drow = out + (size_t)r * CC + cb * 64;
        *(float4*)(drow + tx * 4) =
            make_float4(acc[ii][0] + bv0[0], acc[ii][1] + bv0[1],
                        acc[ii][2] + bv0[2], acc[ii][3] + bv0[3]);
        *(float4*)(drow + tx * 4 + 32) =
            make_float4(acc[ii][4] + bv1[0], acc[ii][5] + bv1[1],
                        acc[ii][6] + bv1[2], acc[ii][7] + bv1[3]);
    }
}

// ---------------------------------------------------------------------------
// Flash attention (fp32, causal). BQ=128 queries per block, k-tiles of 64.
// 128 threads: tx=tid&7 (8 cols, split {tx*4, tx*4+32}), ty=tid>>3 (16 rows of 8).
// smem: Qs[d][i] 64x128 | Ks[d][j] 64x64 | Vs[j][d] 64x64 | Ps[j][i] 64x128 = 96KB
// ---------------------------------------------------------------------------

__global__ void __launch_bounds__(128) attn_kernel()
{
    extern __shared__ float sm[];
    float* Qs = sm;                 // [64][128] (Qs[d][i])
    float* Ks = Qs + 64 * 128;      // [64][64]  (Ks[d][j])
    float* Vs = Ks + 64 * 64;       // [64][64]  (Vs[j][d])
    float* Ps = Vs + 64 * 64;       // [64][128] (Ps[j][i])

    const int qt = (gridDim.x - 1) - blockIdx.x;   // heavy tiles first
    const int bh = blockIdx.y;
    const float* qb = g_q + (size_t)bh * TT * DH;
    const float* kb = g_k + (size_t)bh * TT * DH;
    const float* vb = g_v + (size_t)bh * TT * DH;

    const int tid = threadIdx.x;
    const int tx = tid & 7;
    const int ty = tid >> 3;

    // Load + transpose Q tile (pre-scaled by 1/sqrt(64))
#pragma unroll
    for (int l = 0; l < 16; l++) {
        int lin = (tid + l * 128) * 4;
        int i  = lin >> 6;        // 0..127
        int d0 = lin & 63;
        float4 v = *(const float4*)(qb + (size_t)(qt * 128 + i) * DH + d0);
        Qs[(d0 + 0) * 128 + i] = v.x * 0.125f;
        Qs[(d0 + 1) * 128 + i] = v.y * 0.125f;
        Qs[(d0 + 2) * 128 + i] = v.z * 0.125f;
        Qs[(d0 + 3) * 128 + i] = v.w * 0.125f;
    }

    float o[8][8];
    float mrow[8], lrow[8];
#pragma unroll
    for (int ii = 0; ii < 8; ii++) {
#pragma unroll
        for (int dd = 0; dd < 8; dd++) o[ii][dd] = 0.0f;
        mrow[ii] = -1e30f;
        lrow[ii] = 0.0f;
    }

    const int ktiles = 2 * qt + 2;
    for (int kt = 0; kt < ktiles; kt++) {
        __syncthreads();   // previous O-phase done reading Vs/Ps
        // load K (transposed) and V (natural)
#pragma unroll
        for (int l = 0; l < 8; l++) {
            int lin = (tid + l * 128) * 4;
            int j  = lin >> 6;       // 0..63
            int d0 = lin & 63;
            const float* kr = kb + (size_t)(kt * 64 + j) * DH + d0;
            float4 kv = *(const float4*)kr;
            Ks[(d0 + 0) * 64 + j] = kv.x;
            Ks[(d0 + 1) * 64 + j] = kv.y;
            Ks[(d0 + 2) * 64 + j] = kv.z;
            Ks[(d0 + 3) * 64 + j] = kv.w;
            const float* vr = vb + (size_t)(kt * 64 + j) * DH + d0;
            *(float4*)(Vs + j * 64 + d0) = *(const float4*)vr;
        }
        __syncthreads();

        // S = Q K^T
        float s[8][8];
#pragma unroll
        for (int ii = 0; ii < 8; ii++)
#pragma unroll
            for (int jj = 0; jj < 8; jj++) s[ii][jj] = 0.0f;

#pragma unroll 8
        for (int d = 0; d < 64; d++) {
            float4 a0 = *(const float4*)(Qs + d * 128 + ty * 8);
            float4 a1 = *(const float4*)(Qs + d * 128 + ty * 8 + 4);
            float4 b0 = *(const float4*)(Ks + d * 64 + tx * 4);
            float4 b1 = *(const float4*)(Ks + d * 64 + tx * 4 + 32);
            float a[8] = {a0.x, a0.y, a0.z, a0.w, a1.x, a1.y, a1.z, a1.w};
            float b[8] = {b0.x, b0.y, b0.z, b0.w, b1.x, b1.y, b1.z, b1.w};
#pragma unroll
            for (int ii = 0; ii < 8; ii++)
#pragma unroll
                for (int jj = 0; jj < 8; jj++)
                    s[ii][jj] += a[ii] * b[jj];
        }

        // causal mask (only near the diagonal)
        if (kt >= 2 * qt) {
#pragma unroll
            for (int ii = 0; ii < 8; ii++) {
                int iq = qt * 128 + ty * 8 + ii;
#pragma unroll
                for (int jj = 0; jj < 8; jj++) {
                    int jk = kt * 64 + tx * 4 + (jj & 3) + ((jj >> 2) << 5);
                    if (jk > iq) s[ii][jj] = -1e30f;
                }
            }
        }

        // online softmax
#pragma unroll
        for (int ii = 0; ii < 8; ii++) {
            float tmax = s[ii][0];
#pragma unroll
            for (int jj = 1; jj < 8; jj++) tmax = fmaxf(tmax, s[ii][jj]);
            tmax = fmaxf(tmax, __shfl_xor_sync(0xffffffffu, tmax, 1));
            tmax = fmaxf(tmax, __shfl_xor_sync(0xffffffffu, tmax, 2));
            tmax = fmaxf(tmax, __shfl_xor_sync(0xffffffffu, tmax, 4));
            float mnew = fmaxf(mrow[ii], tmax);
            float alpha = __expf(mrow[ii] - mnew);
            mrow[ii] = mnew;
            float rsum = 0.0f;
#pragma unroll
            for (int jj = 0; jj < 8; jj++) {
                float p = __expf(s[ii][jj] - mnew);
                s[ii][jj] = p;
                rsum += p;
            }
            rsum += __shfl_xor_sync(0xffffffffu, rsum, 1);
            rsum += __shfl_xor_sync(0xffffffffu, rsum, 2);
            rsum += __shfl_xor_sync(0xffffffffu, rsum, 4);
            lrow[ii] = lrow[ii] * alpha + rsum;
#pragma unroll
            for (int dd = 0; dd < 8; dd++) o[ii][dd] *= alpha;
        }

        // stage P (transposed) to smem
#pragma unroll
        for (int jj = 0; jj < 8; jj++) {
            int j = tx * 4 + (jj & 3) + ((jj >> 2) << 5);
#pragma unroll
            for (int ii = 0; ii < 8; ii++)
                Ps[j * 128 + ty * 8 + ii] = s[ii][jj];
        }
        __syncthreads();

        // O += P V
#pragma unroll 8
        for (int j = 0; j < 64; j++) {
            float4 p0 = *(const float4*)(Ps + j * 128 + ty * 8);
            float4 p1 = *(const float4*)(Ps + j * 128 + ty * 8 + 4);
            float4 v0 = *(const float4*)(Vs + j * 64 + tx * 4);
            float4 v1 = *(const float4*)(Vs + j * 64 + tx * 4 + 32);
            float p[8] = {p0.x, p0.y, p0.z, p0.w, p1.x, p1.y, p1.z, p1.w};
            float v[8] = {v0.x, v0.y, v0.z, v0.w, v1.x, v1.y, v1.z, v1.w};
#pragma unroll
            for (int ii = 0; ii < 8; ii++)
#pragma unroll
                for (int dd = 0; dd < 8; dd++)
                    o[ii][dd] += p[ii] * v[dd];
        }
    }

    // finalize: write to g_y[b*T+t][h*64+d]
    const int b = bh / HH;
    const int h = bh % HH;
#pragma unroll
    for (int ii = 0; ii < 8; ii++) {
        float inv = 1.0f / lrow[ii];
        int t = qt * 128 + ty * 8 + ii;
        float* drow = g_y + (size_t)(b * TT + t) * CC + h * DH;
        *(float4*)(drow + tx * 4) =
            make_float4(o[ii][0] * inv, o[ii][1] * inv,
                        o[ii][2] * inv, o[ii][3] * inv);
        *(float4*)(drow + tx * 4 + 32) =
            make_float4(o[ii][4] * inv, o[ii][5] * inv,
                        o[ii][6] * inv, o[ii][7] * inv);
    }
}

// ---------------------------------------------------------------------------

extern "C" void kernel_launch(void* const* d_in, const int* in_sizes, int n_in,
                              void* d_out, int out_size)
{
    const float* x  = (const float*)d_in[0];
    const float* Wk = (const float*)d_in[1];
    const float* Wq = (const float*)d_in[2];
    const float* Wv = (const float*)d_in[3];
    const float* Wp = (const float*)d_in[4];
    const float* bp = (const float*)d_in[5];
    float* out = (float*)d_out;

    // QKV projections: grid (heads=12, row-tiles=64, z=3 for q/k/v)
    qkv_gemm_kernel<<<dim3(12, 64, 3), 128>>>(x, Wq, Wk, Wv);

    // Flash attention: grid (q-tiles=32, b*h=24), 96KB dynamic smem
    const int attn_smem = 24576 * sizeof(float);   // 96KB
    cudaFuncSetAttribute(attn_kernel,
                         cudaFuncAttributeMaxDynamicSharedMemorySize, attn_smem);
    attn_kernel<<<dim3(32, 24), 128, attn_smem>>>();

    // Output projection + bias
    proj_gemm_kernel<<<dim3(12, 64), 128>>>(Wp, bp, out);
}

// round 3
// speedup vs baseline: 1.0080x; 1.0080x over previous
#include <cuda_runtime.h>
#include <cuda_bf16.h>

// Problem constants
#define BB   2
#define TT   4096
#define CC   768
#define HH   12
#define DH   64
#define BT   (BB*TT)          // 8192

// Scratch (device globals; allocation-free rule)
__device__ float g_q[BB*HH*TT*DH];   // [b*H+h][t][d]
__device__ float g_k[BB*HH*TT*DH];
__device__ float g_v[BB*HH*TT*DH];
__device__ float g_y[BT*CC];         // [b*T+t][c]

// ---------------------------------------------------------------------------
// GEMM (NT): out[r,c] = sum_k A[r,k] * W[c,k]
// Tile: 128(M) x 64(N), BK=16, 128 threads, 8x8 per thread.
// Column ownership split {tx*4 .. tx*4+3} U {tx*4+32 .. tx*4+35} -> conflict-free
// float4 smem loads in the inner loop.
// ---------------------------------------------------------------------------

__global__ void __launch_bounds__(128) qkv_gemm_kernel(
    const float* __restrict__ X,
    const float* __restrict__ Wq_,
    const float* __restrict__ Wk_,
    const float* __restrict__ Wv_)
{
    __shared__ float As[16][128];
    __shared__ float Bs[16][64];

    const int z  = blockIdx.z;
    const float* W = (z == 0) ? Wq_ : (z == 1) ? Wk_ : Wv_;
    float* dst     = (z == 0) ? g_q : (z == 1) ? g_k : g_v;

    const int cb = blockIdx.x;   // head index (64 cols == one head)
    const int rb = blockIdx.y;   // 0..63 (row tiles of 128)
    const int tid = threadIdx.x;
    const int tx = tid & 7;
    const int ty = tid >> 3;

    const float* Abase = X + (size_t)rb * 128 * CC;
    const float* Bbase = W + (size_t)cb * 64 * CC;

    float acc[8][8];
#pragma unroll
    for (int i = 0; i < 8; i++)
#pragma unroll
        for (int j = 0; j < 8; j++) acc[i][j] = 0.0f;

    const int mld = tid >> 2;           // 0..31
    const int k0  = (tid & 3) * 4;      // 0,4,8,12

    for (int kc = 0; kc < CC / 16; kc++) {
        const float* Ap = Abase + kc * 16;
#pragma unroll
        for (int l = 0; l < 4; l++) {
            int m = mld + l * 32;
            float4 v = *(const float4*)(Ap + (size_t)m * CC + k0);
            As[k0 + 0][m] = v.x; As[k0 + 1][m] = v.y;
            As[k0 + 2][m] = v.z; As[k0 + 3][m] = v.w;
        }
        const float* Bp = Bbase + kc * 16;
#pragma unroll
        for (int l = 0; l < 2; l++) {
            int n = mld + l * 32;
            float4 v = *(const float4*)(Bp + (size_t)n * CC + k0);
            Bs[k0 + 0][n] = v.x; Bs[k0 + 1][n] = v.y;
            Bs[k0 + 2][n] = v.z; Bs[k0 + 3][n] = v.w;
        }
        __syncthreads();
#pragma unroll
        for (int kk = 0; kk < 16; kk++) {
            float4 a0 = *(const float4*)&As[kk][ty * 8];
            float4 a1 = *(const float4*)&As[kk][ty * 8 + 4];
            float4 b0 = *(const float4*)&Bs[kk][tx * 4];
            float4 b1 = *(const float4*)&Bs[kk][tx * 4 + 32];
            float a[8] = {a0.x, a0.y, a0.z, a0.w, a1.x, a1.y, a1.z, a1.w};
            float b[8] = {b0.x, b0.y, b0.z, b0.w, b1.x, b1.y, b1.z, b1.w};
#pragma unroll
            for (int ii = 0; ii < 8; ii++)
#pragma unroll
                for (int jj = 0; jj < 8; jj++)
                    acc[ii][jj] += a[ii] * b[jj];
        }
        __syncthreads();
    }

    // Write to [b*H+h][t][d]; cols of this block == head cb, d == j.
#pragma unroll
    for (int ii = 0; ii < 8; ii++) {
        int r = rb * 128 + ty * 8 + ii;
        int b = r >> 12;
        int t = r & (TT - 1);
        float* drow = dst + ((size_t)(b * HH + cb) * TT + t) * DH;
        *(float4*)(drow + tx * 4) =
            make_float4(acc[ii][0], acc[ii][1], acc[ii][2], acc[ii][3]);
        *(float4*)(drow + tx * 4 + 32) =
            make_float4(acc[ii][4], acc[ii][5], acc[ii][6], acc[ii][7]);
    }
}

__global__ void __launch_bounds__(128) proj_gemm_kernel(
    const float* __restrict__ Wp,
    const float* __restrict__ bp,
    float* __restrict__ out)
{
    __shared__ float As[16][128];
    __shared__ float Bs[16][64];

    const int cb = blockIdx.x;
    const int rb = blockIdx.y;
    const int tid = threadIdx.x;
    const int tx = tid & 7;
    const int ty = tid >> 3;

    const float* Abase = g_y + (size_t)rb * 128 * CC;
    const float* Bbase = Wp + (size_t)cb * 64 * CC;

    float acc[8][8];
#pragma unroll
    for (int i = 0; i < 8; i++)
#pragma unroll
        for (int j = 0; j < 8; j++) acc[i][j] = 0.0f;

    const int mld = tid >> 2;
    const int k0  = (tid & 3) * 4;

    for (int kc = 0; kc < CC / 16; kc++) {
        const float* Ap = Abase + kc * 16;
#pragma unroll
        for (int l = 0; l < 4; l++) {
            int m = mld + l * 32;
            float4 v = *(const float4*)(Ap + (size_t)m * CC + k0);
            As[k0 + 0][m] = v.x; As[k0 + 1][m] = v.y;
            As[k0 + 2][m] = v.z; As[k0 + 3][m] = v.w;
        }
        const float* Bp = Bbase + kc * 16;
#pragma unroll
        for (int l = 0; l < 2; l++) {
            int n = mld + l * 32;
            float4 v = *(const float4*)(Bp + (size_t)n * CC + k0);
            Bs[k0 + 0][n] = v.x; Bs[k0 + 1][n] = v.y;
            Bs[k0 + 2][n] = v.z; Bs[k0 + 3][n] = v.w;
        }
        __syncthreads();
#pragma unroll
        for (int kk = 0; kk < 16; kk++) {
            float4 a0 = *(const float4*)&As[kk][ty * 8];
            float4 a1 = *(const float4*)&As[kk][ty * 8 + 4];
            float4 b0 = *(const float4*)&Bs[kk][tx * 4];
            float4 b1 = *(const float4*)&Bs[kk][tx * 4 + 32];
            float a[8] = {a0.x, a0.y, a0.z, a0.w, a1.x, a1.y, a1.z, a1.w};
            float b[8] = {b0.x, b0.y, b0.z, b0.w, b1.x, b1.y, b1.z, b1.w};
#pragma unroll
            for (int ii = 0; ii < 8; ii++)
#pragma unroll
                for (int jj = 0; jj < 8; jj++)
                    acc[ii][jj] += a[ii] * b[jj];
        }
        __syncthreads();
    }

    // bias
    float bv0[4], bv1[4];
#pragma unroll
    for (int q = 0; q < 4; q++) {
        bv0[q] = bp[cb * 64 + tx * 4 + q];
        bv1[q] = bp[cb * 64 + tx * 4 + 32 + q];
    }

#pragma unroll
    for (int ii = 0; ii < 8; ii++) {
        int r = rb * 128 + ty * 8 + ii;
        float* drow = out + (size_t)r * CC + cb * 64;
        *(float4*)(drow + tx * 4) =
            make_float4(acc[ii][0] + bv0[0], acc[ii][1] + bv0[1],
                        acc[ii][2] + bv0[2], acc[ii][3] + bv0[3]);
        *(float4*)(drow + tx * 4 + 32) =
            make_float4(acc[ii][4] + bv1[0], acc[ii][5] + bv1[1],
                        acc[ii][6] + bv1[2], acc[ii][7] + bv1[3]);
    }
}

// ---------------------------------------------------------------------------
// Flash attention (fp32, causal). BQ=128 queries per block, k-tiles of 64.
// 128 threads: tx=tid&7 (8 cols, split {tx*4, tx*4+32}), ty=tid>>3 (16 rows of 8).
// smem: Qs[d][i] 64x128 | Ks[d][j] 64x64 | Vs[j][d] 64x64 | Ps[j][i] 64x128 = 96KB
// ---------------------------------------------------------------------------

__global__ void __launch_bounds__(128) attn_kernel()
{
    extern __shared__ float sm[];
    float* Qs = sm;                 // [64][128] (Qs[d][i])
    float* Ks = Qs + 64 * 128;      // [64][64]  (Ks[d][j])
    float* Vs = Ks + 64 * 64;       // [64][64]  (Vs[j][d])
    float* Ps = Vs + 64 * 64;       // [64][128] (Ps[j][i])

    const int qt = (gridDim.x - 1) - blockIdx.x;   // heavy tiles first
    const int bh = blockIdx.y;
    const float* qb = g_q + (size_t)bh * TT * DH;
    const float* kb = g_k + (size_t)bh * TT * DH;
    const float* vb = g_v + (size_t)bh * TT * DH;

    const int tid = threadIdx.x;
    const int tx = tid & 7;
    const int ty = tid >> 3;

    // Load + transpose Q tile (pre-scaled by 1/sqrt(64))
#pragma unroll
    for (int l = 0; l < 16; l++) {
        int lin = (tid + l * 128) * 4;
        int i  = lin >> 6;        // 0..127
        int d0 = lin & 63;
        float4 v = *(const float4*)(qb + (size_t)(qt * 128 + i) * DH + d0);
        Qs[(d0 + 0) * 128 + i] = v.x * 0.125f;
        Qs[(d0 + 1) * 128 + i] = v.y * 0.125f;
        Qs[(d0 + 2) * 128 + i] = v.z * 0.125f;
        Qs[(d0 + 3) * 128 + i] = v.w * 0.125f;
    }

    float o[8][8];
    float mrow[8], lrow[8];
#pragma unroll
    for (int ii = 0; ii < 8; ii++) {
#pragma unroll
        for (int dd = 0; dd < 8; dd++) o[ii][dd] = 0.0f;
        mrow[ii] = -1e30f;
        lrow[ii] = 0.0f;
    }

    const int ktiles = 2 * qt + 2;
    for (int kt = 0; kt < ktiles; kt++) {
        __syncthreads();   // previous O-phase done reading Vs/Ps
        // load K (transposed) and V (natural)
#pragma unroll
        for (int l = 0; l < 8; l++) {
            int lin = (tid + l * 128) * 4;
            int j  = lin >> 6;       // 0..63
            int d0 = lin & 63;
            const float* kr = kb + (size_t)(kt * 64 + j) * DH + d0;
            float4 kv = *(const float4*)kr;
            Ks[(d0 + 0) * 64 + j] = kv.x;
            Ks[(d0 + 1) * 64 + j] = kv.y;
            Ks[(d0 + 2) * 64 + j] = kv.z;
            Ks[(d0 + 3) * 64 + j] = kv.w;
            const float* vr = vb + (size_t)(kt * 64 + j) * DH + d0;
            *(float4*)(Vs + j * 64 + d0) = *(const float4*)vr;
        }
        __syncthreads();

        // S = Q K^T
        float s[8][8];
#pragma unroll
        for (int ii = 0; ii < 8; ii++)
#pragma unroll
            for (int jj = 0; jj < 8; jj++) s[ii][jj] = 0.0f;

#pragma unroll 8
        for (int d = 0; d < 64; d++) {
            float4 a0 = *(const float4*)(Qs + d * 128 + ty * 8);
            float4 a1 = *(const float4*)(Qs + d * 128 + ty * 8 + 4);
            float4 b0 = *(const float4*)(Ks + d * 64 + tx * 4);
            float4 b1 = *(const float4*)(Ks + d * 64 + tx * 4 + 32);
            float a[8] = {a0.x, a0.y, a0.z, a0.w, a1.x, a1.y, a1.z, a1.w};
            float b[8] = {b0.x, b0.y, b0.z, b0.w, b1.x, b1.y, b1.z, b1.w};
#pragma unroll
            for (int ii = 0; ii < 8; ii++)
#pragma unroll
                for (int jj = 0; jj < 8; jj++)
                    s[ii][jj] += a[ii] * b[jj];
        }

        // causal mask (only near the diagonal)
        if (kt >= 2 * qt) {
#pragma unroll
            for (int ii = 0; ii < 8; ii++) {
                int iq = qt * 128 + ty * 8 + ii;
#pragma unroll
                for (int jj = 0; jj < 8; jj++) {
                    int jk = kt * 64 + tx * 4 + (jj & 3) + ((jj >> 2) << 5);
                    if (jk > iq) s[ii][jj] = -1e30f;
                }
            }
        }

        // online softmax
#pragma unroll
        for (int ii = 0; ii < 8; ii++) {
            float tmax = s[ii][0];
#pragma unroll
            for (int jj = 1; jj < 8; jj++) tmax = fmaxf(tmax, s[ii][jj]);
            tmax = fmaxf(tmax, __shfl_xor_sync(0xffffffffu, tmax, 1));
            tmax = fmaxf(tmax, __shfl_xor_sync(0xffffffffu, tmax, 2));
            tmax = fmaxf(tmax, __shfl_xor_sync(0xffffffffu, tmax, 4));
            float mnew = fmaxf(mrow[ii], tmax);
            float alpha = __expf(mrow[ii] - mnew);
            mrow[ii] = mnew;
            float rsum = 0.0f;
#pragma unroll
            for (int jj = 0; jj < 8; jj++) {
                float p = __expf(s[ii][jj] - mnew);
                s[ii][jj] = p;
                rsum += p;
            }
            rsum += __shfl_xor_sync(0xffffffffu, rsum, 1);
            rsum += __shfl_xor_sync(0xffffffffu, rsum, 2);
            rsum += __shfl_xor_sync(0xffffffffu, rsum, 4);
            lrow[ii] = lrow[ii] * alpha + rsum;
#pragma unroll
            for (int dd = 0; dd < 8; dd++) o[ii][dd] *= alpha;
        }

        // stage P (transposed) to smem
#pragma unroll
        for (int jj = 0; jj < 8; jj++) {
            int j = tx * 4 + (jj & 3) + ((jj >> 2) << 5);
#pragma unroll
            for (int ii = 0; ii < 8; ii++)
                Ps[j * 128 + ty * 8 + ii] = s[ii][jj];
        }
        __syncthreads();

        // O += P V
#pragma unroll 8
        for (int j = 0; j < 64; j++) {
            float4 p0 = *(const float4*)(Ps + j * 128 + ty * 8);
            float4 p1 = *(const float4*)(Ps + j * 128 + ty * 8 + 4);
            float4 v0 = *(const float4*)(Vs + j * 64 + tx * 4);
            float4 v1 = *(const float4*)(Vs + j * 64 + tx * 4 + 32);
            float p[8] = {p0.x, p0.y, p0.z, p0.w, p1.x, p1.y, p1.z, p1.w};
            float v[8] = {v0.x, v0.y, v0.z, v0.w, v1.x, v1.y, v1.z, v1.w};
#pragma unroll
            for (int ii = 0; ii < 8; ii++)
#pragma unroll
                for (int dd = 0; dd < 8; dd++)
                    o[ii][dd] += p[ii] * v[dd];
        }
    }

    // finalize: write to g_y[b*T+t][h*64+d]
    const int b = bh / HH;
    const int h = bh % HH;
#pragma unroll
    for (int ii = 0; ii < 8; ii++) {
        float inv = 1.0f / lrow[ii];
        int t = qt * 128 + ty * 8 + ii;
        float* drow = g_y + (size_t)(b * TT + t) * CC + h * DH;
        *(float4*)(drow + tx * 4) =
            make_float4(o[ii][0] * inv, o[ii][1] * inv,
                        o[ii][2] * inv, o[ii][3] * inv);
        *(float4*)(drow + tx * 4 + 32) =
            make_float4(o[ii][4] * inv, o[ii][5] * inv,
                        o[ii][6] * inv, o[ii][7] * inv);
    }
}

// ---------------------------------------------------------------------------

extern "C" void kernel_launch(void* const* d_in, const int* in_sizes, int n_in,
                              void* d_out, int out_size)
{
    const float* x  = (const float*)d_in[0];
    const float* Wk = (const float*)d_in[1];
    const float* Wq = (const float*)d_in[2];
    const float* Wv = (const float*)d_in[3];
    const float* Wp = (const float*)d_in[4];
    const float* bp = (const float*)d_in[5];
    float* out = (float*)d_out;

    // QKV projections: grid (heads=12, row-tiles=64, z=3 for q/k/v)
    qkv_gemm_kernel<<<dim3(12, 64, 3), 128>>>(x, Wq, Wk, Wv);

    // Flash attention: grid (q-tiles=32, b*h=24), 96KB dynamic smem
    const int attn_smem = 24576 * sizeof(float);   // 96KB
    cudaFuncSetAttribute(attn_kernel,
                         cudaFuncAttributeMaxDynamicSharedMemorySize, attn_smem);
    attn_kernel<<<dim3(32, 24), 128, attn_smem>>>();

    // Output projection + bias
    proj_gemm_kernel<<<dim3(12, 64), 128>>>(Wp, bp, out);
}

// round 5
// speedup vs baseline: 1.1972x; 1.1877x over previous
#include <cuda_runtime.h>
#include <cuda_bf16.h>
#include <cstdint>

// Problem constants
#define BB   2
#define TT   4096
#define CC   768
#define HH   12
#define DH   64
#define BT   (BB*TT)          // 8192

// Scratch (device globals; allocation-free rule)
__device__ float g_q[BB*HH*TT*DH];   // [b*H+h][t][d]
__device__ float g_k[BB*HH*TT*DH];
__device__ float g_v[BB*HH*TT*DH];
__device__ float g_y[BT*CC];         // [b*T+t][c]

// ---------------------------------------------------------------------------
// Fast exp on the FMA pipe (no MUFU). |rel err| < 2e-6 for x <= 0.
// exp(x) = 2^y, y = x*log2e; y = i + f, f in [-0.5,0.5];
// 2^f by degree-5 Taylor; 2^i by exponent-bit add.
// ---------------------------------------------------------------------------
__device__ __forceinline__ float fexp(float x) {
    float y = fmaxf(x * 1.4426950408889634f, -126.0f);
    float t = y + 12582912.0f;            // 2^23 + 2^22 : round-to-nearest-int
    int   i = __float_as_int(t);          // low bits hold the integer
    float f = y - (t - 12582912.0f);      // f in [-0.5, 0.5]
    float p =             1.3333558146e-3f;
    p = fmaf(p, f, 9.6181291076e-3f);
    p = fmaf(p, f, 5.5504108664e-2f);
    p = fmaf(p, f, 2.4022650696e-1f);
    p = fmaf(p, f, 6.9314718056e-1f);
    p = fmaf(p, f, 1.0f);
    return __int_as_float(__float_as_int(p) + (i << 23));
}

// ---------------------------------------------------------------------------
// tf32 mma.sync helpers (compute_103-safe PTX; runs on tensor pipe as HMMA)
// D(m16n8) += A(m16k8,row) * B(k8n8,col), fp32 accum.
// A frag: a0=(g,   tg) a1=(g+8, tg) a2=(g,   tg+4) a3=(g+8, tg+4)
// B frag: b0=(k=tg, n=g) b1=(k=tg+4, n=g)
// C frag: c0=(g, 2tg) c1=(g, 2tg+1) c2=(g+8, 2tg) c3=(g+8, 2tg+1)
//   where g = lane/4, tg = lane%4.
// ---------------------------------------------------------------------------
#define MMA_TF32(c, a, b) \
    asm volatile("mma.sync.aligned.m16n8k8.row.col.f32.tf32.tf32.f32 " \
                 "{%0,%1,%2,%3}, {%4,%5,%6,%7}, {%8,%9}, {%0,%1,%2,%3};" \
                 : "+f"((c)[0]), "+f"((c)[1]), "+f"((c)[2]), "+f"((c)[3]) \
                 : "r"((a)[0]), "r"((a)[1]), "r"((a)[2]), "r"((a)[3]), \
                   "r"((b)[0]), "r"((b)[1]))

__device__ __forceinline__ uint32_t to_tf32(float v) {
    uint32_t u;
    asm("cvt.rna.tf32.f32 %0, %1;" : "=r"(u) : "f"(v));
    return u;
}

// Scatter a gmem float4 (row r, cols 4*c4..4*c4+3 of a [rows x 16] slab)
// into A-fragment-ordered smem: buf[((ks*8+mt)*32 + t)*4 + reg]
__device__ __forceinline__ void scatterA(uint32_t* buf, int row, int c4, float4 v) {
    const int mt = row >> 4, rl = row & 15;
    float vv[4] = {v.x, v.y, v.z, v.w};
#pragma unroll
    for (int e = 0; e < 4; e++) {
        int c  = c4 * 4 + e;
        int ks = c >> 3, cl = c & 7;
        int t  = (rl & 7) * 4 + (cl & 3);
        int rg = (rl >> 3) + 2 * (cl >> 2);
        buf[((ks * 8 + mt) * 32 + t) * 4 + rg] = to_tf32(vv[e]);
    }
}

// B (weights W[n][k]): buf[((ks*16+nt)*32 + t)*2 + reg]
__device__ __forceinline__ void scatterB(uint32_t* buf, int n, int c4, float4 v) {
    const int nt = n >> 3, nl = n & 7;
    float vv[4] = {v.x, v.y, v.z, v.w};
#pragma unroll
    for (int e = 0; e < 4; e++) {
        int c  = c4 * 4 + e;
        int ks = c >> 3, kl = c & 7;
        int t  = nl * 4 + (kl & 3);
        int rg = kl >> 2;
        buf[((ks * 16 + nt) * 32 + t) * 2 + rg] = to_tf32(vv[e]);
    }
}

// ---------------------------------------------------------------------------
// tf32 GEMM (NT): out[r,c] = sum_k A[r,k]*W[c,k]. BM=128 BN=128 BK=16.
// 256 threads = 8 warps (2x4): warp tile 64(m) x 32(n) = 4x4 mma tiles.
// smem double-buffered, fragment-ordered (conflict-free LDS.128/64 in loop).
// ---------------------------------------------------------------------------
struct MmaCore {
    uint32_t (*sA)[2048];
    uint32_t (*sB)[2048];
};

__device__ __forceinline__ void gemm_mma_loop(
    const float* __restrict__ Ab, const float* __restrict__ Bb,
    uint32_t sA[2][2048], uint32_t sB[2][2048],
    float c[4][4][4], int tid)
{
    const int lane   = tid & 31;
    const int wid    = tid >> 5;
    const int warp_m = wid >> 2;      // 0..1
    const int warp_n = wid & 3;       // 0..3

    const int rowA = tid >> 2;        // 0..63 (and +64)
    const int c4   = tid & 3;
    const float* pA0 = Ab + (size_t)rowA * CC + c4 * 4;
    const float* pA1 = pA0 + (size_t)64 * CC;
    const float* pB0 = Bb + (size_t)rowA * CC + c4 * 4;
    const float* pB1 = pB0 + (size_t)64 * CC;

#pragma unroll
    for (int im = 0; im < 4; im++)
#pragma unroll
        for (int in = 0; in < 4; in++)
#pragma unroll
            for (int k = 0; k < 4; k++) c[im][in][k] = 0.0f;

    // prologue: stage 0
    {
        float4 a0 = *(const float4*)pA0;
        float4 a1 = *(const float4*)pA1;
        float4 b0 = *(const float4*)pB0;
        float4 b1 = *(const float4*)pB1;
        scatterA(sA[0], rowA, c4, a0);
        scatterA(sA[0], rowA + 64, c4, a1);
        scatterB(sB[0], rowA, c4, b0);
        scatterB(sB[0], rowA + 64, c4, b1);
    }
    __syncthreads();

    const int NK = CC / 16;   // 48
    for (int kc = 0; kc < NK; kc++) {
        const int s = kc & 1;
        float4 a0, a1, b0, b1;
        if (kc + 1 < NK) {
            const float* q = pA0 + (kc + 1) * 16;
            a0 = *(const float4*)q;
            a1 = *(const float4*)(q + (size_t)64 * CC);
            const float* r = pB0 + (kc + 1) * 16;
            b0 = *(const float4*)r;
            b1 = *(const float4*)(r + (size_t)64 * CC);
        }

        // compute on stage s
#pragma unroll
        for (int ks = 0; ks < 2; ks++) {
            uint32_t af[4][4], bf[4][2];
#pragma unroll
            for (int im = 0; im < 4; im++) {
                const uint32_t* p = &sA[s][((ks * 8 + warp_m * 4 + im) * 32 + lane) * 4];
                uint4 v = *(const uint4*)p;
                af[im][0] = v.x; af[im][1] = v.y; af[im][2] = v.z; af[im][3] = v.w;
            }
#pragma unroll
            for (int in = 0; in < 4; in++) {
                const uint32_t* p = &sB[s][((ks * 16 + warp_n * 4 + in) * 32 + lane) * 2];
                uint2 v = *(const uint2*)p;
                bf[in][0] = v.x; bf[in][1] = v.y;
            }
#pragma unroll
            for (int im = 0; im < 4; im++)
#pragma unroll
                for (int in = 0; in < 4; in++)
                    MMA_TF32(c[im][in], af[im], bf[in]);
        }

        if (kc + 1 < NK) {
            uint32_t* dA = sA[s ^ 1];
            uint32_t* dB = sB[s ^ 1];
            scatterA(dA, rowA, c4, a0);
            scatterA(dA, rowA + 64, c4, a1);
            scatterB(dB, rowA, c4, b0);
            scatterB(dB, rowA + 64, c4, b1);
        }
        __syncthreads();
    }
}

__global__ void __launch_bounds__(256) qkv_mma_kernel(
    const float* __restrict__ X,
    const float* __restrict__ Wq_,
    const float* __restrict__ Wk_,
    const float* __restrict__ Wv_)
{
    __shared__ uint32_t sA[2][2048];
    __shared__ uint32_t sB[2][2048];

    const int z  = blockIdx.z;
    const float* W = (z == 0) ? Wq_ : (z == 1) ? Wk_ : Wv_;
    float* dst     = (z == 0) ? g_q : (z == 1) ? g_k : g_v;

    const int cb  = blockIdx.x;    // 0..5 : 128 out-cols = 2 heads
    const int rb  = blockIdx.y;    // 0..63
    const int tid = threadIdx.x;

    float c[4][4][4];
    gemm_mma_loop(X + (size_t)rb * 128 * CC, W + (size_t)cb * 128 * CC,
                  sA, sB, c, tid);

    const int lane   = tid & 31;
    const int wid    = tid >> 5;
    const int warp_m = wid >> 2;
    const int warp_n = wid & 3;
    const int g  = lane >> 2;
    const int tg = lane & 3;

#pragma unroll
    for (int im = 0; im < 4; im++) {
        int r0 = rb * 128 + warp_m * 64 + im * 16 + g;
#pragma unroll
        for (int in = 0; in < 4; in++) {
            int colb = warp_n * 32 + in * 8 + 2 * tg;   // 0..127
            int hp   = colb >> 6;                        // head within pair
            int d    = colb & 63;
            // row r0
            {
                int b = r0 >> 12, t = r0 & (TT - 1);
                float* p = dst + ((size_t)(b * HH + cb * 2 + hp) * TT + t) * DH + d;
                *(float2*)p = make_float2(c[im][in][0], c[im][in][1]);
            }
            // row r0+8
            {
                int r1 = r0 + 8;
                int b = r1 >> 12, t = r1 & (TT - 1);
                float* p = dst + ((size_t)(b * HH + cb * 2 + hp) * TT + t) * DH + d;
                *(float2*)p = make_float2(c[im][in][2], c[im][in][3]);
            }
        }
    }
}

__global__ void __launch_bounds__(256) proj_mma_kernel(
    const float* __restrict__ Wp,
    const float* __restrict__ bp,
    float* __restrict__ out)
{
    __shared__ uint32_t sA[2][2048];
    __shared__ uint32_t sB[2][2048];

    const int cb  = blockIdx.x;    // 0..5
    const int rb  = blockIdx.y;    // 0..63
    const int tid = threadIdx.x;

    float c[4][4][4];
    gemm_mma_loop(g_y + (size_t)rb * 128 * CC, Wp + (size_t)cb * 128 * CC,
                  sA, sB, c, tid);

    const int lane   = tid & 31;
    const int wid    = tid >> 5;
    const int warp_m = wid >> 2;
    const int warp_n = wid & 3;
    const int g  = lane >> 2;
    const int tg = lane & 3;

#pragma unroll
    for (int im = 0; im < 4; im++) {
        int r0 = rb * 128 + warp_m * 64 + im * 16 + g;
#pragma unroll
        for (int in = 0; in < 4; in++) {
            int colb = warp_n * 32 + in * 8 + 2 * tg;
            int col  = cb * 128 + colb;
            float b0 = bp[col], b1 = bp[col + 1];
            *(float2*)(out + (size_t)r0 * CC + col) =
                make_float2(c[im][in][0] + b0, c[im][in][1] + b1);
            *(float2*)(out + (size_t)(r0 + 8) * CC + col) =
                make_float2(c[im][in][2] + b0, c[im][in][3] + b1);
        }
    }
}

// ---------------------------------------------------------------------------
// Flash attention (fp32, causal). Same structure as R3 passing version,
// but all exps go through fexp (FMA pipe) instead of MUFU __expf.
// ---------------------------------------------------------------------------

__global__ void __launch_bounds__(128) attn_kernel()
{
    extern __shared__ float sm[];
    float* Qs = sm;                 // [64][128] (Qs[d][i])
    float* Ks = Qs + 64 * 128;      // [64][64]  (Ks[d][j])
    float* Vs = Ks + 64 * 64;       // [64][64]  (Vs[j][d])
    float* Ps = Vs + 64 * 64;       // [64][128] (Ps[j][i])

    const int qt = (gridDim.x - 1) - blockIdx.x;   // heavy tiles first
    const int bh = blockIdx.y;
    const float* qb = g_q + (size_t)bh * TT * DH;
    const float* kb = g_k + (size_t)bh * TT * DH;
    const float* vb = g_v + (size_t)bh * TT * DH;

    const int tid = threadIdx.x;
    const int tx = tid & 7;
    const int ty = tid >> 3;

#pragma unroll
    for (int l = 0; l < 16; l++) {
        int lin = (tid + l * 128) * 4;
        int i  = lin >> 6;
        int d0 = lin & 63;
        float4 v = *(const float4*)(qb + (size_t)(qt * 128 + i) * DH + d0);
        Qs[(d0 + 0) * 128 + i] = v.x * 0.125f;
        Qs[(d0 + 1) * 128 + i] = v.y * 0.125f;
        Qs[(d0 + 2) * 128 + i] = v.z * 0.125f;
        Qs[(d0 + 3) * 128 + i] = v.w * 0.125f;
    }

    float o[8][8];
    float mrow[8], lrow[8];
#pragma unroll
    for (int ii = 0; ii < 8; ii++) {
#pragma unroll
        for (int dd = 0; dd < 8; dd++) o[ii][dd] = 0.0f;
        mrow[ii] = -1e30f;
        lrow[ii] = 0.0f;
    }

    const int ktiles = 2 * qt + 2;
    for (int kt = 0; kt < ktiles; kt++) {
        __syncthreads();
#pragma unroll
        for (int l = 0; l < 8; l++) {
            int lin = (tid + l * 128) * 4;
            int j  = lin >> 6;
            int d0 = lin & 63;
            const float* kr = kb + (size_t)(kt * 64 + j) * DH + d0;
            float4 kv = *(const float4*)kr;
            Ks[(d0 + 0) * 64 + j] = kv.x;
            Ks[(d0 + 1) * 64 + j] = kv.y;
            Ks[(d0 + 2) * 64 + j] = kv.z;
            Ks[(d0 + 3) * 64 + j] = kv.w;
            const float* vr = vb + (size_t)(kt * 64 + j) * DH + d0;
            *(float4*)(Vs + j * 64 + d0) = *(const float4*)vr;
        }
        __syncthreads();

        float s[8][8];
#pragma unroll
        for (int ii = 0; ii < 8; ii++)
#pragma unroll
            for (int jj = 0; jj < 8; jj++) s[ii][jj] = 0.0f;

#pragma unroll 8
        for (int d = 0; d < 64; d++) {
            float4 a0 = *(const float4*)(Qs + d * 128 + ty * 8);
            float4 a1 = *(const float4*)(Qs + d * 128 + ty * 8 + 4);
            float4 b0 = *(const float4*)(Ks + d * 64 + tx * 4);
            float4 b1 = *(const float4*)(Ks + d * 64 + tx * 4 + 32);
            float a[8] = {a0.x, a0.y, a0.z, a0.w, a1.x, a1.y, a1.z, a1.w};
            float b[8] = {b0.x, b0.y, b0.z, b0.w, b1.x, b1.y, b1.z, b1.w};
#pragma unroll
            for (int ii = 0; ii < 8; ii++)
#pragma unroll
                for (int jj = 0; jj < 8; jj++)
                    s[ii][jj] += a[ii] * b[jj];
        }

        if (kt >= 2 * qt) {
#pragma unroll
            for (int ii = 0; ii < 8; ii++) {
                int iq = qt * 128 + ty * 8 + ii;
#pragma unroll
                for (int jj = 0; jj < 8; jj++) {
                    int jk = kt * 64 + tx * 4 + (jj & 3) + ((jj >> 2) << 5);
                    if (jk > iq) s[ii][jj] = -1e30f;
                }
            }
        }

#pragma unroll
        for (int ii = 0; ii < 8; ii++) {
            float tmax = s[ii][0];
#pragma unroll
            for (int jj = 1; jj < 8; jj++) tmax = fmaxf(tmax, s[ii][jj]);
            tmax = fmaxf(tmax, __shfl_xor_sync(0xffffffffu, tmax, 1));
            tmax = fmaxf(tmax, __shfl_xor_sync(0xffffffffu, tmax, 2));
            tmax = fmaxf(tmax, __shfl_xor_sync(0xffffffffu, tmax, 4));
            float mnew = fmaxf(mrow[ii], tmax);
            float alpha = fexp(mrow[ii] - mnew);
            mrow[ii] = mnew;
            float rsum = 0.0f;
#pragma unroll
            for (int jj = 0; jj < 8; jj++) {
                float p = fexp(s[ii][jj] - mnew);
                s[ii][jj] = p;
                rsum += p;
            }
            rsum += __shfl_xor_sync(0xffffffffu, rsum, 1);
            rsum += __shfl_xor_sync(0xffffffffu, rsum, 2);
            rsum += __shfl_xor_sync(0xffffffffu, rsum, 4);
            lrow[ii] = lrow[ii] * alpha + rsum;
#pragma unroll
            for (int dd = 0; dd < 8; dd++) o[ii][dd] *= alpha;
        }

#pragma unroll
        for (int jj = 0; jj < 8; jj++) {
            int j = tx * 4 + (jj & 3) + ((jj >> 2) << 5);
#pragma unroll
            for (int ii = 0; ii < 8; ii++)
                Ps[j * 128 + ty * 8 + ii] = s[ii][jj];
        }
        __syncthreads();

#pragma unroll 8
        for (int j = 0; j < 64; j++) {
            float4 p0 = *(const float4*)(Ps + j * 128 + ty * 8);
            float4 p1 = *(const float4*)(Ps + j * 128 + ty * 8 + 4);
            float4 v0 = *(const float4*)(Vs + j * 64 + tx * 4);
            float4 v1 = *(const float4*)(Vs + j * 64 + tx * 4 + 32);
            float p[8] = {p0.x, p0.y, p0.z, p0.w, p1.x, p1.y, p1.z, p1.w};
            float v[8] = {v0.x, v0.y, v0.z, v0.w, v1.x, v1.y, v1.z, v1.w};
#pragma unroll
            for (int ii = 0; ii < 8; ii++)
#pragma unroll
                for (int dd = 0; dd < 8; dd++)
                    o[ii][dd] += p[ii] * v[dd];
        }
    }

    const int b = bh / HH;
    const int h = bh % HH;
#pragma unroll
    for (int ii = 0; ii < 8; ii++) {
        float inv = 1.0f / lrow[ii];
        int t = qt * 128 + ty * 8 + ii;
        float* drow = g_y + (size_t)(b * TT + t) * CC + h * DH;
        *(float4*)(drow + tx * 4) =
            make_float4(o[ii][0] * inv, o[ii][1] * inv,
                        o[ii][2] * inv, o[ii][3] * inv);
        *(float4*)(drow + tx * 4 + 32) =
            make_float4(o[ii][4] * inv, o[ii][5] * inv,
                        o[ii][6] * inv, o[ii][7] * inv);
    }
}

// ---------------------------------------------------------------------------

extern "C" void kernel_launch(void* const* d_in, const int* in_sizes, int n_in,
                              void* d_out, int out_size)
{
    const float* x  = (const float*)d_in[0];
    const float* Wk = (const float*)d_in[1];
    const float* Wq = (const float*)d_in[2];
    const float* Wv = (const float*)d_in[3];
    const float* Wp = (const float*)d_in[4];
    const float* bp = (const float*)d_in[5];
    float* out = (float*)d_out;

    cudaFuncSetAttribute(attn_kernel,
                         cudaFuncAttributeMaxDynamicSharedMemorySize, 24576 * 4);

    // QKV projections (tf32 mma.sync): grid (col-tiles=6, row-tiles=64, z=3)
    qkv_mma_kernel<<<dim3(6, 64, 3), 256>>>(x, Wq, Wk, Wv);

    // Flash attention: grid (q-tiles=32, b*h=24), 96KB dynamic smem
    attn_kernel<<<dim3(32, 24), 128, 24576 * 4>>>();

    // Output projection + bias (tf32 mma.sync)
    proj_mma_kernel<<<dim3(6, 64), 256>>>(Wp, bp, out);
}

// round 6
// speedup vs baseline: 2.1568x; 1.8015x over previous
#include <cuda_runtime.h>
#include <cuda_bf16.h>
#include <cstdint>

// Problem constants
#define BB   2
#define TT   4096
#define CC   768
#define HH   12
#define DH   64
#define BT   (BB*TT)          // 8192

// Scratch (device globals; allocation-free rule)
__device__ float g_q[BB*HH*TT*DH];   // [b*H+h][t][d]
__device__ float g_k[BB*HH*TT*DH];
__device__ float g_v[BB*HH*TT*DH];
__device__ float g_y[BT*CC];         // [b*T+t][c]

// ---------------------------------------------------------------------------
// Fast exp on the FMA pipe (no MUFU). |rel err| < 2e-6 for x <= 0.
// ---------------------------------------------------------------------------
__device__ __forceinline__ float fexp(float x) {
    float y = fmaxf(x * 1.4426950408889634f, -126.0f);
    float t = y + 12582912.0f;            // 2^23 + 2^22 : round-to-nearest-int
    int   i = __float_as_int(t);
    float f = y - (t - 12582912.0f);      // f in [-0.5, 0.5]
    float p =             1.3333558146e-3f;
    p = fmaf(p, f, 9.6181291076e-3f);
    p = fmaf(p, f, 5.5504108664e-2f);
    p = fmaf(p, f, 2.4022650696e-1f);
    p = fmaf(p, f, 6.9314718056e-1f);
    p = fmaf(p, f, 1.0f);
    return __int_as_float(__float_as_int(p) + (i << 23));
}

// ---------------------------------------------------------------------------
// tf32 mma.sync helpers.
// A frag: a0=(g, tg) a1=(g+8, tg) a2=(g, tg+4) a3=(g+8, tg+4)   [m, k]
// B frag: b0=(k=tg, n=g) b1=(k=tg+4, n=g)
// C frag: c0=(g, 2tg) c1=(g, 2tg+1) c2=(g+8, 2tg) c3=(g+8, 2tg+1)
//   g = lane/4, tg = lane%4.
// ---------------------------------------------------------------------------
#define MMA_TF32(c, a, b) \
    asm volatile("mma.sync.aligned.m16n8k8.row.col.f32.tf32.tf32.f32 " \
                 "{%0,%1,%2,%3}, {%4,%5,%6,%7}, {%8,%9}, {%0,%1,%2,%3};" \
                 : "+f"((c)[0]), "+f"((c)[1]), "+f"((c)[2]), "+f"((c)[3]) \
                 : "r"((a)[0]), "r"((a)[1]), "r"((a)[2]), "r"((a)[3]), \
                   "r"((b)[0]), "r"((b)[1]))

__device__ __forceinline__ uint32_t to_tf32(float v) {
    uint32_t u;
    asm("cvt.rna.tf32.f32 %0, %1;" : "=r"(u) : "f"(v));
    return u;
}

// Fragment-order scatter for GEMM kernels (unchanged from R5)
__device__ __forceinline__ void scatterA(uint32_t* buf, int row, int c4, float4 v) {
    const int mt = row >> 4, rl = row & 15;
    float vv[4] = {v.x, v.y, v.z, v.w};
#pragma unroll
    for (int e = 0; e < 4; e++) {
        int c  = c4 * 4 + e;
        int ks = c >> 3, cl = c & 7;
        int t  = (rl & 7) * 4 + (cl & 3);
        int rg = (rl >> 3) + 2 * (cl >> 2);
        buf[((ks * 8 + mt) * 32 + t) * 4 + rg] = to_tf32(vv[e]);
    }
}

__device__ __forceinline__ void scatterB(uint32_t* buf, int n, int c4, float4 v) {
    const int nt = n >> 3, nl = n & 7;
    float vv[4] = {v.x, v.y, v.z, v.w};
#pragma unroll
    for (int e = 0; e < 4; e++) {
        int c  = c4 * 4 + e;
        int ks = c >> 3, kl = c & 7;
        int t  = nl * 4 + (kl & 3);
        int rg = kl >> 2;
        buf[((ks * 16 + nt) * 32 + t) * 2 + rg] = to_tf32(vv[e]);
    }
}

// ---------------------------------------------------------------------------
// tf32 GEMM (NT): out[r,c] = sum_k A[r,k]*W[c,k]. BM=128 BN=128 BK=16.
// ---------------------------------------------------------------------------
__device__ __forceinline__ void gemm_mma_loop(
    const float* __restrict__ Ab, const float* __restrict__ Bb,
    uint32_t sA[2][2048], uint32_t sB[2][2048],
    float c[4][4][4], int tid)
{
    const int lane   = tid & 31;
    const int wid    = tid >> 5;
    const int warp_m = wid >> 2;
    const int warp_n = wid & 3;

    const int rowA = tid >> 2;
    const int c4   = tid & 3;
    const float* pA0 = Ab + (size_t)rowA * CC + c4 * 4;
    const float* pA1 = pA0 + (size_t)64 * CC;
    const float* pB0 = Bb + (size_t)rowA * CC + c4 * 4;
    const float* pB1 = pB0 + (size_t)64 * CC;

#pragma unroll
    for (int im = 0; im < 4; im++)
#pragma unroll
        for (int in = 0; in < 4; in++)
#pragma unroll
            for (int k = 0; k < 4; k++) c[im][in][k] = 0.0f;

    {
        float4 a0 = *(const float4*)pA0;
        float4 a1 = *(const float4*)pA1;
        float4 b0 = *(const float4*)pB0;
        float4 b1 = *(const float4*)pB1;
        scatterA(sA[0], rowA, c4, a0);
        scatterA(sA[0], rowA + 64, c4, a1);
        scatterB(sB[0], rowA, c4, b0);
        scatterB(sB[0], rowA + 64, c4, b1);
    }
    __syncthreads();

    const int NK = CC / 16;   // 48
    for (int kc = 0; kc < NK; kc++) {
        const int s = kc & 1;
        float4 a0, a1, b0, b1;
        if (kc + 1 < NK) {
            const float* q = pA0 + (kc + 1) * 16;
            a0 = *(const float4*)q;
            a1 = *(const float4*)(q + (size_t)64 * CC);
            const float* r = pB0 + (kc + 1) * 16;
            b0 = *(const float4*)r;
            b1 = *(const float4*)(r + (size_t)64 * CC);
        }

#pragma unroll
        for (int ks = 0; ks < 2; ks++) {
            uint32_t af[4][4], bf[4][2];
#pragma unroll
            for (int im = 0; im < 4; im++) {
                const uint32_t* p = &sA[s][((ks * 8 + warp_m * 4 + im) * 32 + lane) * 4];
                uint4 v = *(const uint4*)p;
                af[im][0] = v.x; af[im][1] = v.y; af[im][2] = v.z; af[im][3] = v.w;
            }
#pragma unroll
            for (int in = 0; in < 4; in++) {
                const uint32_t* p = &sB[s][((ks * 16 + warp_n * 4 + in) * 32 + lane) * 2];
                uint2 v = *(const uint2*)p;
                bf[in][0] = v.x; bf[in][1] = v.y;
            }
#pragma unroll
            for (int im = 0; im < 4; im++)
#pragma unroll
                for (int in = 0; in < 4; in++)
                    MMA_TF32(c[im][in], af[im], bf[in]);
        }

        if (kc + 1 < NK) {
            uint32_t* dA = sA[s ^ 1];
            uint32_t* dB = sB[s ^ 1];
            scatterA(dA, rowA, c4, a0);
            scatterA(dA, rowA + 64, c4, a1);
            scatterB(dB, rowA, c4, b0);
            scatterB(dB, rowA + 64, c4, b1);
        }
        __syncthreads();
    }
}

__global__ void __launch_bounds__(256) qkv_mma_kernel(
    const float* __restrict__ X,
    const float* __restrict__ Wq_,
    const float* __restrict__ Wk_,
    const float* __restrict__ Wv_)
{
    __shared__ uint32_t sA[2][2048];
    __shared__ uint32_t sB[2][2048];

    const int z  = blockIdx.z;
    const float* W = (z == 0) ? Wq_ : (z == 1) ? Wk_ : Wv_;
    float* dst     = (z == 0) ? g_q : (z == 1) ? g_k : g_v;

    const int cb  = blockIdx.x;
    const int rb  = blockIdx.y;
    const int tid = threadIdx.x;

    float c[4][4][4];
    gemm_mma_loop(X + (size_t)rb * 128 * CC, W + (size_t)cb * 128 * CC,
                  sA, sB, c, tid);

    const int lane   = tid & 31;
    const int wid    = tid >> 5;
    const int warp_m = wid >> 2;
    const int warp_n = wid & 3;
    const int g  = lane >> 2;
    const int tg = lane & 3;

#pragma unroll
    for (int im = 0; im < 4; im++) {
        int r0 = rb * 128 + warp_m * 64 + im * 16 + g;
#pragma unroll
        for (int in = 0; in < 4; in++) {
            int colb = warp_n * 32 + in * 8 + 2 * tg;
            int hp   = colb >> 6;
            int d    = colb & 63;
            {
                int b = r0 >> 12, t = r0 & (TT - 1);
                float* p = dst + ((size_t)(b * HH + cb * 2 + hp) * TT + t) * DH + d;
                *(float2*)p = make_float2(c[im][in][0], c[im][in][1]);
            }
            {
                int r1 = r0 + 8;
                int b = r1 >> 12, t = r1 & (TT - 1);
                float* p = dst + ((size_t)(b * HH + cb * 2 + hp) * TT + t) * DH + d;
                *(float2*)p = make_float2(c[im][in][2], c[im][in][3]);
            }
        }
    }
}

__global__ void __launch_bounds__(256) proj_mma_kernel(
    const float* __restrict__ Wp,
    const float* __restrict__ bp,
    float* __restrict__ out)
{
    __shared__ uint32_t sA[2][2048];
    __shared__ uint32_t sB[2][2048];

    const int cb  = blockIdx.x;
    const int rb  = blockIdx.y;
    const int tid = threadIdx.x;

    float c[4][4][4];
    gemm_mma_loop(g_y + (size_t)rb * 128 * CC, Wp + (size_t)cb * 128 * CC,
                  sA, sB, c, tid);

    const int lane   = tid & 31;
    const int wid    = tid >> 5;
    const int warp_m = wid >> 2;
    const int warp_n = wid & 3;
    const int g  = lane >> 2;
    const int tg = lane & 3;

#pragma unroll
    for (int im = 0; im < 4; im++) {
        int r0 = rb * 128 + warp_m * 64 + im * 16 + g;
#pragma unroll
        for (int in = 0; in < 4; in++) {
            int colb = warp_n * 32 + in * 8 + 2 * tg;
            int col  = cb * 128 + colb;
            float b0 = bp[col], b1 = bp[col + 1];
            *(float2*)(out + (size_t)r0 * CC + col) =
                make_float2(c[im][in][0] + b0, c[im][in][1] + b1);
            *(float2*)(out + (size_t)(r0 + 8) * CC + col) =
                make_float2(c[im][in][2] + b0, c[im][in][3] + b1);
        }
    }
}

// ---------------------------------------------------------------------------
// Flash attention on tensor pipe (tf32 mma, fp32 accum, causal).
// 256 threads = 8 warps; warp w owns query rows qt*128 + w*16 + [0,16).
// smem (64KB dynamic):
//   sK [4096] u32 : K tile 64x64, B-frag order for S   (n=j, k=d)
//   sV [4096] u32 : V tile 64x64, B-frag order for PV  (n=d, k=j)
//   sP [8192] u32 : per-warp 1024: P 16x64 in A-frag order (also Q staging)
// ---------------------------------------------------------------------------
__global__ void __launch_bounds__(256) attn_mma_kernel()
{
    extern __shared__ uint32_t smem_u[];
    uint32_t* sK = smem_u;            // 4096
    uint32_t* sV = smem_u + 4096;     // 4096
    uint32_t* sP = smem_u + 8192;     // 8192

    const int qt = (gridDim.x - 1) - blockIdx.x;   // heavy tiles first
    const int bh = blockIdx.y;
    const float* qb = g_q + (size_t)bh * TT * DH;
    const float* kb = g_k + (size_t)bh * TT * DH;
    const float* vb = g_v + (size_t)bh * TT * DH;

    const int tid  = threadIdx.x;
    const int w    = tid >> 5;
    const int lane = tid & 31;
    const int g    = lane >> 2;
    const int tg   = lane & 3;

    // ---- Stage Q tile (128x64, pre-scaled) into sP, then to register frags
    float* Qstage = (float*)sP;       // 32KB
#pragma unroll
    for (int l = 0; l < 8; l++) {
        int idx = l * 256 + tid;          // 0..2047 float4s
        int i  = idx >> 4;
        int f4 = idx & 15;
        float4 v = *(const float4*)(qb + (size_t)(qt * 128 + i) * DH + f4 * 4);
        v.x *= 0.125f; v.y *= 0.125f; v.z *= 0.125f; v.w *= 0.125f;
        *(float4*)(Qstage + i * 64 + f4 * 4) = v;
    }
    __syncthreads();

    uint32_t qa[8][4];
    {
        const int r0 = w * 16 + g;
#pragma unroll
        for (int ks = 0; ks < 8; ks++) {
            qa[ks][0] = to_tf32(Qstage[(r0)     * 64 + ks * 8 + tg]);
            qa[ks][1] = to_tf32(Qstage[(r0 + 8) * 64 + ks * 8 + tg]);
            qa[ks][2] = to_tf32(Qstage[(r0)     * 64 + ks * 8 + tg + 4]);
            qa[ks][3] = to_tf32(Qstage[(r0 + 8) * 64 + ks * 8 + tg + 4]);
        }
    }

    float o[8][4];
#pragma unroll
    for (int nt = 0; nt < 8; nt++)
#pragma unroll
        for (int k = 0; k < 4; k++) o[nt][k] = 0.0f;
    float mrowA = -1e30f, mrowB = -1e30f, lrowA = 0.0f, lrowB = 0.0f;

    uint32_t* Pw = sP + w * 1024;
    const int iA = qt * 128 + w * 16 + g;
    const int iB = iA + 8;

    const int ktiles = 2 * qt + 2;
    for (int kt = 0; kt < ktiles; kt++) {
        __syncthreads();   // prev compute done with sK/sV (and Q staging, iter 0)
        // ---- cooperative load + fragment scatter of K and V (tf32)
        const float* kp = kb + (size_t)kt * 64 * DH;
        const float* vp = vb + (size_t)kt * 64 * DH;
#pragma unroll
        for (int l = 0; l < 4; l++) {
            int idx = l * 256 + tid;        // 0..1023
            int j  = idx >> 4;
            int f4 = idx & 15;
            int d0 = f4 * 4;
            float4 kv = *(const float4*)(kp + (size_t)j * 64 + d0);
            float kk[4] = {kv.x, kv.y, kv.z, kv.w};
#pragma unroll
            for (int e = 0; e < 4; e++) {
                int d  = d0 + e;
                int ks = d >> 3, nt = j >> 3;
                int t  = (j & 7) * 4 + (d & 3);
                int rg = (d >> 2) & 1;
                sK[((ks * 8 + nt) * 32 + t) * 2 + rg] = to_tf32(kk[e]);
            }
            float4 vv = *(const float4*)(vp + (size_t)j * 64 + d0);
            float vk[4] = {vv.x, vv.y, vv.z, vv.w};
#pragma unroll
            for (int e = 0; e < 4; e++) {
                int d  = d0 + e;
                int ks = j >> 3, nt = d >> 3;
                int t  = (d & 7) * 4 + (j & 3);
                int rg = (j >> 2) & 1;
                sV[((ks * 8 + nt) * 32 + t) * 2 + rg] = to_tf32(vk[e]);
            }
        }
        __syncthreads();

        // ---- S = Q K^T (16x64 per warp)
        float s[8][4];
#pragma unroll
        for (int nt = 0; nt < 8; nt++)
#pragma unroll
            for (int k = 0; k < 4; k++) s[nt][k] = 0.0f;

#pragma unroll
        for (int ks = 0; ks < 8; ks++) {
#pragma unroll
            for (int nt = 0; nt < 8; nt++) {
                uint2 bv = *(const uint2*)&sK[((ks * 8 + nt) * 32 + lane) * 2];
                uint32_t bf[2] = {bv.x, bv.y};
                MMA_TF32(s[nt], qa[ks], bf);
            }
        }

        // ---- causal mask (only last two k-tiles touch the diagonal)
        if (kt >= 2 * qt) {
#pragma unroll
            for (int nt = 0; nt < 8; nt++) {
                int j0 = kt * 64 + nt * 8 + 2 * tg;
                if (j0     > iA) s[nt][0] = -1e30f;
                if (j0 + 1 > iA) s[nt][1] = -1e30f;
                if (j0     > iB) s[nt][2] = -1e30f;
                if (j0 + 1 > iB) s[nt][3] = -1e30f;
            }
        }

        // ---- online softmax (2 rows per thread, quad reduction)
        float mA = s[0][0], mB = s[0][2];
#pragma unroll
        for (int nt = 0; nt < 8; nt++) {
            mA = fmaxf(mA, fmaxf(s[nt][0], s[nt][1]));
            mB = fmaxf(mB, fmaxf(s[nt][2], s[nt][3]));
        }
        mA = fmaxf(mA, __shfl_xor_sync(0xffffffffu, mA, 1));
        mA = fmaxf(mA, __shfl_xor_sync(0xffffffffu, mA, 2));
        mB = fmaxf(mB, __shfl_xor_sync(0xffffffffu, mB, 1));
        mB = fmaxf(mB, __shfl_xor_sync(0xffffffffu, mB, 2));
        float mnA = fmaxf(mrowA, mA), mnB = fmaxf(mrowB, mB);
        float aA  = fexp(mrowA - mnA), aB = fexp(mrowB - mnB);
        mrowA = mnA; mrowB = mnB;

        float rsA = 0.0f, rsB = 0.0f;
#pragma unroll
        for (int nt = 0; nt < 8; nt++) {
            s[nt][0] = fexp(s[nt][0] - mnA);
            s[nt][1] = fexp(s[nt][1] - mnA);
            s[nt][2] = fexp(s[nt][2] - mnB);
            s[nt][3] = fexp(s[nt][3] - mnB);
            rsA += s[nt][0] + s[nt][1];
            rsB += s[nt][2] + s[nt][3];
        }
        rsA += __shfl_xor_sync(0xffffffffu, rsA, 1);
        rsA += __shfl_xor_sync(0xffffffffu, rsA, 2);
        rsB += __shfl_xor_sync(0xffffffffu, rsB, 1);
        rsB += __shfl_xor_sync(0xffffffffu, rsB, 2);
        lrowA = lrowA * aA + rsA;
        lrowB = lrowB * aB + rsB;
#pragma unroll
        for (int nt = 0; nt < 8; nt++) {
            o[nt][0] *= aA; o[nt][1] *= aA;
            o[nt][2] *= aB; o[nt][3] *= aB;
        }

        // ---- stage P (tf32) to warp-private smem in A-frag order
        // For C elem (rl, c): t=(rl&7)*4+(c&3), rg=(rl>>3)+2*((c&7)>>2).
        // c in {2tg, 2tg+1}: rg0=2*(tg>>1); rows g / g+8 pack into STS.64 pairs.
        {
            const int t0  = g * 4 + ((2 * tg) & 3);
            const int rg0 = 2 * (tg >> 1);
#pragma unroll
            for (int nt = 0; nt < 8; nt++) {
                uint32_t p00 = to_tf32(s[nt][0]);
                uint32_t p10 = to_tf32(s[nt][2]);
                uint32_t p01 = to_tf32(s[nt][1]);
                uint32_t p11 = to_tf32(s[nt][3]);
                *(uint2*)&Pw[(nt * 32 + t0) * 4 + rg0]       = make_uint2(p00, p10);
                *(uint2*)&Pw[(nt * 32 + t0 + 1) * 4 + rg0]   = make_uint2(p01, p11);
            }
        }
        __syncwarp();

        // ---- O += P V (16x64 per warp)
#pragma unroll
        for (int ks = 0; ks < 8; ks++) {
            uint4 av = *(const uint4*)&Pw[(ks * 32 + lane) * 4];
            uint32_t af[4] = {av.x, av.y, av.z, av.w};
#pragma unroll
            for (int nt = 0; nt < 8; nt++) {
                uint2 bv = *(const uint2*)&sV[((ks * 8 + nt) * 32 + lane) * 2];
                uint32_t bf[2] = {bv.x, bv.y};
                MMA_TF32(o[nt], af, bf);
            }
        }
        __syncwarp();   // P reads done before next iteration overwrites
    }

    // ---- finalize: g_y[b*T+t][h*64+d]
    const int b = bh / HH;
    const int h = bh % HH;
    const float invA = 1.0f / lrowA;
    const float invB = 1.0f / lrowB;
    float* rowA = g_y + (size_t)(b * TT + iA) * CC + h * DH;
    float* rowB = g_y + (size_t)(b * TT + iB) * CC + h * DH;
#pragma unroll
    for (int nt = 0; nt < 8; nt++) {
        int d = nt * 8 + 2 * tg;
        *(float2*)(rowA + d) = make_float2(o[nt][0] * invA, o[nt][1] * invA);
        *(float2*)(rowB + d) = make_float2(o[nt][2] * invB, o[nt][3] * invB);
    }
}

// ---------------------------------------------------------------------------

extern "C" void kernel_launch(void* const* d_in, const int* in_sizes, int n_in,
                              void* d_out, int out_size)
{
    const float* x  = (const float*)d_in[0];
    const float* Wk = (const float*)d_in[1];
    const float* Wq = (const float*)d_in[2];
    const float* Wv = (const float*)d_in[3];
    const float* Wp = (const float*)d_in[4];
    const float* bp = (const float*)d_in[5];
    float* out = (float*)d_out;

    const int attn_smem = 65536;
    cudaFuncSetAttribute(attn_mma_kernel,
                         cudaFuncAttributeMaxDynamicSharedMemorySize, attn_smem);

    // QKV projections (tf32 mma.sync)
    qkv_mma_kernel<<<dim3(6, 64, 3), 256>>>(x, Wq, Wk, Wv);

    // Flash attention on tensor pipe
    attn_mma_kernel<<<dim3(32, 24), 256, attn_smem>>>();

    // Output projection + bias (tf32 mma.sync)
    proj_mma_kernel<<<dim3(6, 64), 256>>>(Wp, bp, out);
}